// round 15
// baseline (speedup 1.0000x reference)
#include <cuda_runtime.h>
#include <cuda_bf16.h>
#include <cuda_fp16.h>
#include <math.h>
#include <stdint.h>

#define NN 50000
#define NE 600000
#define IN_DIM 512
#define HIDDEN 128
#define OUT_DIM 64
#define N_LAYERS 3
#define EPS 0.1f

// ---------------- scratch (static device globals; no allocation) ----------------
__device__ int   g_cnt[NN];
__device__ int   g_off[NN + 4];
__device__ float g_dinv[NN];
__device__ int   g_csr_src[NE];
__device__ float g_norm[NE];
__device__ float g_alA[NN];
__device__ float g_arA[NN];
__device__ float g_alB[NN];
__device__ float g_arB[NN];
__device__ float g_raw[(size_t)NN * HIDDEN];   // fp32 h from GEMM1 (skip input)
__device__ float g_hF[(size_t)NN * HIDDEN];    // fp32 final-layer h for GEMM2
__device__ uint2 g_h16R[(size_t)NN * 32];      // fp16 mirrors (32 uint2 = 128 halfs/row)
__device__ uint2 g_h16A[(size_t)NN * 32];
__device__ uint2 g_h16B[(size_t)NN * 32];
#define APITCH 34
#define CHUNK_U2 (128 * APITCH)
#define MBLK ((NN + 127) / 128)                // 391
__device__ uint2 g_wsplit[8 * CHUNK_U2];
__device__ uint2 g_xsplit[(size_t)MBLK * 8 * CHUNK_U2];   // X pre-split, tile-layout

// ---------------- CSR build ----------------
__global__ void k_count(const int* __restrict__ dst, int E) {
    int e = blockIdx.x * blockDim.x + threadIdx.x;
    if (e < E) atomicAdd(&g_cnt[dst[e]], 1);
}

__global__ __launch_bounds__(1024) void k_scan() {
    __shared__ int sh_warp[32];
    __shared__ int sh_carry;
    const int tid = threadIdx.x, lane = tid & 31, wid = tid >> 5;
    if (tid == 0) sh_carry = 0;
    __syncthreads();
    for (int base = 0; base < NN; base += 4096) {
        int idx = base + tid * 4;
        int4 c = make_int4(0, 0, 0, 0);
        if (idx < NN) c = *(const int4*)&g_cnt[idx];
        int t = c.x + c.y + c.z + c.w;
        int v = t;
#pragma unroll
        for (int o = 1; o < 32; o <<= 1) {
            int tt = __shfl_up_sync(0xffffffffu, v, o);
            if (lane >= o) v += tt;
        }
        if (lane == 31) sh_warp[wid] = v;
        __syncthreads();
        if (wid == 0) {
            int s = sh_warp[lane];
#pragma unroll
            for (int o = 1; o < 32; o <<= 1) {
                int tt = __shfl_up_sync(0xffffffffu, s, o);
                if (lane >= o) s += tt;
            }
            sh_warp[lane] = s;
        }
        __syncthreads();
        int warpoff = (wid > 0) ? sh_warp[wid - 1] : 0;
        int incl = v + warpoff;
        int excl = incl - t + sh_carry;
        if (idx < NN) {
            int4 off;
            off.x = excl;
            off.y = off.x + c.x;
            off.z = off.y + c.y;
            off.w = off.z + c.z;
            *(int4*)&g_off[idx] = off;
            float4 dv;
            dv.x = c.x ? rsqrtf((float)c.x) : 0.f;
            dv.y = c.y ? rsqrtf((float)c.y) : 0.f;
            dv.z = c.z ? rsqrtf((float)c.z) : 0.f;
            dv.w = c.w ? rsqrtf((float)c.w) : 0.f;
            *(float4*)&g_dinv[idx] = dv;
            *(int4*)&g_cnt[idx] = make_int4(0, 0, 0, 0);
        }
        __syncthreads();
        if (tid == 1023) sh_carry += incl;
        __syncthreads();
    }
    if (tid == 0) g_off[NN] = sh_carry;
}

__global__ void k_fill(const int* __restrict__ src, const int* __restrict__ dst, int E) {
    int e = blockIdx.x * blockDim.x + threadIdx.x;
    if (e < E) {
        int s = src[e], d = dst[e];
        int pos = g_off[d] + atomicAdd(&g_cnt[d], 1);
        g_csr_src[pos] = s;
        g_norm[pos] = g_dinv[s] * g_dinv[d];
    }
}

// ---------------- packing helpers ----------------
__device__ __forceinline__ uint32_t pkbf(float a, float b) {
    __nv_bfloat162 t;
    t.x = __float2bfloat16_rn(a);
    t.y = __float2bfloat16_rn(b);
    return *(uint32_t*)&t;
}

// ---------------- W split + interleave ----------------
__global__ void k_wconv(const float* __restrict__ W) {
    int i = blockIdx.x * blockDim.x + threadIdx.x;
    if (i >= HIDDEN * 256) return;
    int m = i >> 8;
    int pg = i & 255;
    int c = pg >> 5;
    int p = pg & 31;
    float w0 = W[m * IN_DIM + c * 64 + 2 * p];
    float w1 = W[m * IN_DIM + c * 64 + 2 * p + 1];
    float h0 = __bfloat162float(__float2bfloat16_rn(w0));
    float h1 = __bfloat162float(__float2bfloat16_rn(w1));
    uint2 v;
    v.x = pkbf(w0, w1);
    v.y = pkbf(w0 - h0, w1 - h1);
    g_wsplit[(size_t)c * CHUNK_U2 + m * APITCH + p] = v;
}

// ---------------- X split + interleave (tile layout, streamed once) ----------------
__global__ __launch_bounds__(256) void k_xconv(const float* __restrict__ X, int M) {
    size_t i = (size_t)blockIdx.x * blockDim.x + threadIdx.x;
    if (i >= (size_t)MBLK * 128 * 256) return;
    int row = (int)(i >> 8);
    int kpg = (int)(i & 255);
    int chunk = kpg >> 5;
    int p = kpg & 31;
    int sr = row < M ? row : M - 1;
    float w0 = X[(size_t)sr * IN_DIM + chunk * 64 + 2 * p];
    float w1 = X[(size_t)sr * IN_DIM + chunk * 64 + 2 * p + 1];
    float h0 = __bfloat162float(__float2bfloat16_rn(w0));
    float h1 = __bfloat162float(__float2bfloat16_rn(w1));
    uint2 v;
    v.x = pkbf(w0, w1);
    v.y = pkbf(w0 - h0, w1 - h1);
    int mb = row >> 7;
    int rl = row & 127;
    g_xsplit[((size_t)(mb * 8 + chunk) * 128 + rl) * APITCH + p] = v;
}

// ---------------- GEMM1: mma.sync bf16-split, all-cp.async staging, occ-2 ----------------
#define GEMM1_DSMEM (2 * CHUNK_U2 * 8)

__device__ __forceinline__ void mma_bf16(float* c, uint32_t a0, uint32_t a1,
                                         uint32_t a2, uint32_t a3,
                                         uint32_t b0, uint32_t b1) {
    asm volatile(
        "mma.sync.aligned.m16n8k16.row.col.f32.bf16.bf16.f32 "
        "{%0,%1,%2,%3}, {%4,%5,%6,%7}, {%8,%9}, {%0,%1,%2,%3};"
        : "+f"(c[0]), "+f"(c[1]), "+f"(c[2]), "+f"(c[3])
        : "r"(a0), "r"(a1), "r"(a2), "r"(a3), "r"(b0), "r"(b1));
}

__global__ __launch_bounds__(256, 2) void k_gemm1_mma(const float* __restrict__ Bias,
                                                      const float* __restrict__ attL,
                                                      const float* __restrict__ attR,
                                                      float* __restrict__ al_out,
                                                      float* __restrict__ ar_out,
                                                      float* __restrict__ O,
                                                      uint32_t* __restrict__ O16,
                                                      int M) {
    extern __shared__ uint2 sm[];
    uint2* smA = sm;
    uint2* smW = sm + CHUNK_U2;
    __shared__ float sBias[128], sAtl[128], sAtr[128];

    const int tid = threadIdx.x;
    const int wt = tid >> 5;
    const int lane = tid & 31;
    const int r = lane >> 2;
    const int q = lane & 3;
    const int m0 = blockIdx.x * 128;

    uint32_t smA_u32, smW_u32;
    asm("{ .reg .u64 t; cvta.to.shared.u64 t, %1; cvt.u32.u64 %0, t; }"
        : "=r"(smA_u32) : "l"((void*)smA));
    asm("{ .reg .u64 t; cvta.to.shared.u64 t, %1; cvt.u32.u64 %0, t; }"
        : "=r"(smW_u32) : "l"((void*)smW));

    if (tid < 128) {
        sBias[tid] = Bias[tid];
        sAtl[tid] = attL[tid];
        sAtr[tid] = attR[tid];
    }

    float acc[16][4];
#pragma unroll
    for (int i = 0; i < 16; i++)
#pragma unroll
        for (int j = 0; j < 4; j++) acc[i][j] = 0.f;

    // issue chunk-0 loads (A and W) in one group
    {
        const uint2* gA = g_xsplit + (size_t)(blockIdx.x * 8) * CHUNK_U2;
        const uint2* gW = g_wsplit;
        for (int i = tid; i < 2176; i += 256) {
            asm volatile("cp.async.cg.shared.global [%0], [%1], 16;"
                         :: "r"(smA_u32 + i * 16), "l"(gA + (size_t)i * 2));
            asm volatile("cp.async.cg.shared.global [%0], [%1], 16;"
                         :: "r"(smW_u32 + i * 16), "l"(gW + (size_t)i * 2));
        }
        asm volatile("cp.async.commit_group;" ::: "memory");
    }

    for (int c = 0; c < IN_DIM / 64; c++) {
        asm volatile("cp.async.wait_group 0;" ::: "memory");
        __syncthreads();

#pragma unroll
        for (int k16 = 0; k16 < 4; k16++) {
            const int kp = k16 * 8;
            uint2 pa0 = smA[(wt * 16 + r) * APITCH + kp + q];
            uint2 pa1 = smA[(wt * 16 + r + 8) * APITCH + kp + q];
            uint2 pa2 = smA[(wt * 16 + r) * APITCH + kp + q + 4];
            uint2 pa3 = smA[(wt * 16 + r + 8) * APITCH + kp + q + 4];
#pragma unroll
            for (int nt = 0; nt < 16; nt++) {
                uint2 pb0 = smW[(nt * 8 + r) * APITCH + kp + q];
                uint2 pb1 = smW[(nt * 8 + r) * APITCH + kp + q + 4];
                mma_bf16(acc[nt], pa0.x, pa1.x, pa2.x, pa3.x, pb0.x, pb1.x);
                mma_bf16(acc[nt], pa0.x, pa1.x, pa2.x, pa3.x, pb0.y, pb1.y);
                mma_bf16(acc[nt], pa0.y, pa1.y, pa2.y, pa3.y, pb0.x, pb1.x);
            }
        }
        __syncthreads();
        if (c + 1 < IN_DIM / 64) {
            const uint2* gA = g_xsplit + (size_t)(blockIdx.x * 8 + c + 1) * CHUNK_U2;
            const uint2* gW = g_wsplit + (size_t)(c + 1) * CHUNK_U2;
            for (int i = tid; i < 2176; i += 256) {
                asm volatile("cp.async.cg.shared.global [%0], [%1], 16;"
                             :: "r"(smA_u32 + i * 16), "l"(gA + (size_t)i * 2));
                asm volatile("cp.async.cg.shared.global [%0], [%1], 16;"
                             :: "r"(smW_u32 + i * 16), "l"(gW + (size_t)i * 2));
            }
            asm volatile("cp.async.commit_group;" ::: "memory");
        }
    }

    int mlo = m0 + wt * 16 + r;
    int mhi = mlo + 8;
    float slLo = 0.f, srLo = 0.f, slHi = 0.f, srHi = 0.f;
#pragma unroll
    for (int nt = 0; nt < 16; nt++) {
        int c0 = nt * 8 + q * 2;
        float b0 = sBias[c0], b1 = sBias[c0 + 1];
        float l0 = sAtl[c0], l1 = sAtl[c0 + 1];
        float t0 = sAtr[c0], t1 = sAtr[c0 + 1];
        float v0 = fmaxf(acc[nt][0] + b0, 0.f);
        float v1 = fmaxf(acc[nt][1] + b1, 0.f);
        float v2 = fmaxf(acc[nt][2] + b0, 0.f);
        float v3 = fmaxf(acc[nt][3] + b1, 0.f);
        slLo = fmaf(v0, l0, fmaf(v1, l1, slLo));
        srLo = fmaf(v0, t0, fmaf(v1, t1, srLo));
        slHi = fmaf(v2, l0, fmaf(v3, l1, slHi));
        srHi = fmaf(v2, t0, fmaf(v3, t1, srHi));
        if (mlo < M) {
            *(float2*)(O + (size_t)mlo * HIDDEN + c0) = make_float2(v0, v1);
            __half2 hp = __floats2half2_rn(v0, v1);
            O16[((size_t)mlo * HIDDEN + c0) >> 1] = *(uint32_t*)&hp;
        }
        if (mhi < M) {
            *(float2*)(O + (size_t)mhi * HIDDEN + c0) = make_float2(v2, v3);
            __half2 hp = __floats2half2_rn(v2, v3);
            O16[((size_t)mhi * HIDDEN + c0) >> 1] = *(uint32_t*)&hp;
        }
    }
#pragma unroll
    for (int o = 1; o <= 2; o <<= 1) {
        slLo += __shfl_xor_sync(0xffffffffu, slLo, o);
        srLo += __shfl_xor_sync(0xffffffffu, srLo, o);
        slHi += __shfl_xor_sync(0xffffffffu, slHi, o);
        srHi += __shfl_xor_sync(0xffffffffu, srHi, o);
    }
    if (q == 0) {
        if (mlo < M) { al_out[mlo] = slLo; ar_out[mlo] = srLo; }
        if (mhi < M) { al_out[mhi] = slHi; ar_out[mhi] = srHi; }
    }
}

// ---------------- aggregation: warp-per-node, fp16 rows, 2-way unrolled loads ----------------
__global__ __launch_bounds__(256) void k_gather(const uint2* __restrict__ h16,
                                                const float4* __restrict__ raw4,
                                                uint2* __restrict__ o16,
                                                float4* __restrict__ o4,
                                                const float* __restrict__ al_in,
                                                const float* __restrict__ ar_in,
                                                const float4* __restrict__ attl_next,
                                                const float4* __restrict__ attr_next,
                                                float* __restrict__ al_out,
                                                float* __restrict__ ar_out,
                                                int M) {
    int w = (blockIdx.x * blockDim.x + threadIdx.x) >> 5;
    int lane = threadIdx.x & 31;
    if (w >= M) return;
    int b = g_off[w];
    int e = g_off[w + 1];
    float ar_w = ar_in[w];
    float4 r = raw4[(size_t)w * 32 + lane];
    float4 acc;
    acc.x = EPS * r.x; acc.y = EPS * r.y; acc.z = EPS * r.z; acc.w = EPS * r.w;

    for (int j0 = b; j0 < e; j0 += 32) {
        int jj = j0 + lane;
        float cl = 0.f;
        int sl = 0;
        if (jj < e) {
            sl = __ldg(&g_csr_src[jj]);
            float nrm = __ldg(&g_norm[jj]);
            cl = tanhf(al_in[sl] + ar_w) * nrm;
        }
        int cnt = min(32, e - j0);
        int k = 0;
        for (; k + 2 <= cnt; k += 2) {
            float c0 = __shfl_sync(0xffffffffu, cl, k);
            float c1 = __shfl_sync(0xffffffffu, cl, k + 1);
            int s0 = __shfl_sync(0xffffffffu, sl, k);
            int s1 = __shfl_sync(0xffffffffu, sl, k + 1);
            uint2 hv0 = __ldg(&h16[(size_t)s0 * 32 + lane]);
            uint2 hv1 = __ldg(&h16[(size_t)s1 * 32 + lane]);
            float2 a0 = __half22float2(*(__half2*)&hv0.x);
            float2 a1 = __half22float2(*(__half2*)&hv0.y);
            float2 b0 = __half22float2(*(__half2*)&hv1.x);
            float2 b1 = __half22float2(*(__half2*)&hv1.y);
            acc.x = fmaf(c0, a0.x, acc.x);
            acc.y = fmaf(c0, a0.y, acc.y);
            acc.z = fmaf(c0, a1.x, acc.z);
            acc.w = fmaf(c0, a1.y, acc.w);
            acc.x = fmaf(c1, b0.x, acc.x);
            acc.y = fmaf(c1, b0.y, acc.y);
            acc.z = fmaf(c1, b1.x, acc.z);
            acc.w = fmaf(c1, b1.y, acc.w);
        }
        if (k < cnt) {
            float c = __shfl_sync(0xffffffffu, cl, k);
            int s = __shfl_sync(0xffffffffu, sl, k);
            uint2 hv = __ldg(&h16[(size_t)s * 32 + lane]);
            float2 f0 = __half22float2(*(__half2*)&hv.x);
            float2 f1 = __half22float2(*(__half2*)&hv.y);
            acc.x = fmaf(c, f0.x, acc.x);
            acc.y = fmaf(c, f0.y, acc.y);
            acc.z = fmaf(c, f1.x, acc.z);
            acc.w = fmaf(c, f1.y, acc.w);
        }
    }
    if (o16) {
        __half2 p0 = __floats2half2_rn(acc.x, acc.y);
        __half2 p1 = __floats2half2_rn(acc.z, acc.w);
        uint2 ov;
        ov.x = *(uint32_t*)&p0;
        ov.y = *(uint32_t*)&p1;
        o16[(size_t)w * 32 + lane] = ov;
    }
    if (o4) o4[(size_t)w * 32 + lane] = acc;

    if (attl_next) {
        float4 wl = attl_next[lane];
        float4 wr = attr_next[lane];
        float a = acc.x * wl.x + acc.y * wl.y + acc.z * wl.z + acc.w * wl.w;
        float bb = acc.x * wr.x + acc.y * wr.y + acc.z * wr.z + acc.w * wr.w;
#pragma unroll
        for (int o = 16; o > 0; o >>= 1) {
            a += __shfl_xor_sync(0xffffffffu, a, o);
            bb += __shfl_xor_sync(0xffffffffu, bb, o);
        }
        if (lane == 0) { al_out[w] = a; ar_out[w] = bb; }
    }
}

// ---------------- GEMM2 + fused log_softmax ----------------
__global__ __launch_bounds__(256) void k_gemm2(const float* __restrict__ H,
                                               const float* __restrict__ W,
                                               const float* __restrict__ B,
                                               float* __restrict__ Emb,
                                               float* __restrict__ Ls, int M) {
    __shared__ float As[16][64];
    __shared__ float Bs[16][64];
    const int tid = threadIdx.x;
    const int m0 = blockIdx.x * 64;
    const int lr = tid >> 2;
    const int lk = (tid & 3) * 4;
    const int tm = (tid >> 4) * 4;
    const int tn = (tid & 15) * 4;

    int gm = m0 + lr;
    if (gm >= M) gm = M - 1;
    const float* hp = H + (size_t)gm * HIDDEN + lk;
    const float* wp = W + (size_t)lr * HIDDEN + lk;

    float acc[4][4];
#pragma unroll
    for (int i = 0; i < 4; i++)
#pragma unroll
        for (int j = 0; j < 4; j++) acc[i][j] = 0.f;

    for (int k0 = 0; k0 < HIDDEN; k0 += 16) {
        float4 xa = *(const float4*)(hp + k0);
        float4 wa = *(const float4*)(wp + k0);
        As[lk + 0][lr] = xa.x; As[lk + 1][lr] = xa.y;
        As[lk + 2][lr] = xa.z; As[lk + 3][lr] = xa.w;
        Bs[lk + 0][lr] = wa.x; Bs[lk + 1][lr] = wa.y;
        Bs[lk + 2][lr] = wa.z; Bs[lk + 3][lr] = wa.w;
        __syncthreads();
#pragma unroll
        for (int kk = 0; kk < 16; kk++) {
            float4 a4 = *(const float4*)&As[kk][tm];
            float4 b4 = *(const float4*)&Bs[kk][tn];
            float a[4] = {a4.x, a4.y, a4.z, a4.w};
            float b[4] = {b4.x, b4.y, b4.z, b4.w};
#pragma unroll
            for (int i = 0; i < 4; i++)
#pragma unroll
                for (int j = 0; j < 4; j++) acc[i][j] = fmaf(a[i], b[j], acc[i][j]);
        }
        __syncthreads();
    }

    float bias[4];
#pragma unroll
    for (int j = 0; j < 4; j++) bias[j] = B[tn + j];

#pragma unroll
    for (int i = 0; i < 4; i++) {
        int m = m0 + tm + i;
        float v[4];
#pragma unroll
        for (int j = 0; j < 4; j++) v[j] = acc[i][j] + bias[j];
        float mx = fmaxf(fmaxf(v[0], v[1]), fmaxf(v[2], v[3]));
#pragma unroll
        for (int o = 8; o > 0; o >>= 1) mx = fmaxf(mx, __shfl_xor_sync(0xffffffffu, mx, o));
        float s = expf(v[0] - mx) + expf(v[1] - mx) + expf(v[2] - mx) + expf(v[3] - mx);
#pragma unroll
        for (int o = 8; o > 0; o >>= 1) s += __shfl_xor_sync(0xffffffffu, s, o);
        float lse = mx + logf(s);
        if (m < M) {
            *(float4*)(Emb + (size_t)m * OUT_DIM + tn) = make_float4(v[0], v[1], v[2], v[3]);
            *(float4*)(Ls + (size_t)m * OUT_DIM + tn) =
                make_float4(v[0] - lse, v[1] - lse, v[2] - lse, v[3] - lse);
        }
    }
}

// ---------------- launch ----------------
extern "C" void kernel_launch(void* const* d_in, const int* in_sizes, int n_in,
                              void* d_out, int out_size) {
    const float* x    = (const float*)d_in[0];
    const int*   ei   = (const int*)  d_in[1];
    const float* t1w  = (const float*)d_in[2];
    const float* t1b  = (const float*)d_in[3];
    const float* t2w  = (const float*)d_in[4];
    const float* t2b  = (const float*)d_in[5];
    const float* attl = (const float*)d_in[6];
    const float* attr = (const float*)d_in[7];

    const int M = in_sizes[0] / IN_DIM;   // 50000
    const int E = in_sizes[1] / 2;        // 600000
    const int* src = ei;
    const int* dst = ei + E;

    float *raw, *hF, *alA, *arA, *alB, *arB;
    uint2 *h16R, *h16A, *h16B;
    int* cntp;
    cudaGetSymbolAddress((void**)&raw, g_raw);
    cudaGetSymbolAddress((void**)&hF, g_hF);
    cudaGetSymbolAddress((void**)&h16R, g_h16R);
    cudaGetSymbolAddress((void**)&h16A, g_h16A);
    cudaGetSymbolAddress((void**)&h16B, g_h16B);
    cudaGetSymbolAddress((void**)&alA, g_alA);
    cudaGetSymbolAddress((void**)&arA, g_arA);
    cudaGetSymbolAddress((void**)&alB, g_alB);
    cudaGetSymbolAddress((void**)&arB, g_arB);
    cudaGetSymbolAddress((void**)&cntp, g_cnt);

    float* out_ls  = (float*)d_out;
    float* out_emb = out_ls + (size_t)M * OUT_DIM;

    cudaFuncSetAttribute(k_gemm1_mma, cudaFuncAttributeMaxDynamicSharedMemorySize,
                         GEMM1_DSMEM);

    static cudaStream_t s2 = nullptr;
    static cudaEvent_t evFork = nullptr, evJoin = nullptr;
    if (!s2) {
        cudaStreamCreateWithFlags(&s2, cudaStreamNonBlocking);
        cudaEventCreateWithFlags(&evFork, cudaEventDisableTiming);
        cudaEventCreateWithFlags(&evJoin, cudaEventDisableTiming);
    }

    // k_gemm1_mma stays the 4th kernel launch (ncu capture target).
    k_wconv<<<(HIDDEN * 256 + 255) / 256, 256>>>(t1w);                  // (1) main
    k_xconv<<<MBLK * 128, 256>>>(x, M);                                 // (2) main

    cudaEventRecord(evFork, 0);
    cudaStreamWaitEvent(s2, evFork, 0);
    cudaMemsetAsync(cntp, 0, NN * sizeof(int), s2);
    k_count<<<(E + 255) / 256, 256, 0, s2>>>(dst, E);                   // (3) s2

    k_gemm1_mma<<<(M + 127) / 128, 256, GEMM1_DSMEM>>>(t1b, attl, attr, alA, arA,
                                                       raw, (uint32_t*)h16R, M);  // (4) main

    k_scan<<<1, 1024, 0, s2>>>();                                       // (5) s2
    k_fill<<<(E + 255) / 256, 256, 0, s2>>>(src, dst, E);               // (6) s2
    cudaEventRecord(evJoin, s2);
    cudaStreamWaitEvent(0, evJoin, 0);

    // layer 0: read h16R -> write h16A (fp16 only)
    k_gather<<<((size_t)M * 32 + 255) / 256, 256>>>(h16R, (const float4*)raw,
                                                    h16A, nullptr,
                                                    alA, arA,
                                                    (const float4*)(attl + HIDDEN),
                                                    (const float4*)(attr + HIDDEN),
                                                    alB, arB, M);
    // layer 1: read h16A -> write h16B (fp16 only)
    k_gather<<<((size_t)M * 32 + 255) / 256, 256>>>(h16A, (const float4*)raw,
                                                    h16B, nullptr,
                                                    alB, arB,
                                                    (const float4*)(attl + 2 * HIDDEN),
                                                    (const float4*)(attr + 2 * HIDDEN),
                                                    alA, arA, M);
    // layer 2: read h16B -> write fp32 hF (for GEMM2)
    k_gather<<<((size_t)M * 32 + 255) / 256, 256>>>(h16B, (const float4*)raw,
                                                    nullptr, (float4*)hF,
                                                    alA, arA,
                                                    nullptr, nullptr,
                                                    nullptr, nullptr, M);

    k_gemm2<<<(M + 63) / 64, 256>>>(hF, t2w, t2b, out_emb, out_ls, M);
}

// round 16
// speedup vs baseline: 1.5697x; 1.5697x over previous
#include <cuda_runtime.h>
#include <cuda_bf16.h>
#include <cuda_fp16.h>
#include <math.h>
#include <stdint.h>

#define NN 50000
#define NE 600000
#define IN_DIM 512
#define HIDDEN 128
#define OUT_DIM 64
#define N_LAYERS 3
#define EPS 0.1f

// ---------------- scratch (static device globals; no allocation) ----------------
__device__ int   g_cnt[NN];
__device__ int   g_off[NN + 4];
__device__ float g_dinv[NN];
__device__ int   g_csr_src[NE];
__device__ float g_norm[NE];
__device__ float g_alA[NN];
__device__ float g_arA[NN];
__device__ float g_alB[NN];
__device__ float g_arB[NN];
__device__ float g_raw[(size_t)NN * HIDDEN];   // fp32 h from GEMM1 (skip input)
__device__ float g_hF[(size_t)NN * HIDDEN];    // fp32 final-layer h for GEMM2
__device__ uint2 g_h16R[(size_t)NN * 32];      // fp16 mirrors (32 uint2 = 128 halfs/row)
__device__ uint2 g_h16A[(size_t)NN * 32];
__device__ uint2 g_h16B[(size_t)NN * 32];
#define APITCH 34
#define CHUNK_U2 (128 * APITCH)
__device__ uint2 g_wsplit[8 * CHUNK_U2];

// Within each k16 group of 8 kpairs, permute so kpairs (q, q+4) are adjacent:
// slot(p) = ((p&3)<<1) | ((p>>2)&1)  -> pair q at 2q, pair q+4 at 2q+1.
__host__ __device__ __forceinline__ int kperm(int p) {
    return (p & ~7) | (((p & 3) << 1) | ((p >> 2) & 1));
}

// ---------------- CSR build ----------------
__global__ void k_count(const int* __restrict__ dst, int E) {
    int e = blockIdx.x * blockDim.x + threadIdx.x;
    if (e < E) atomicAdd(&g_cnt[dst[e]], 1);
}

__global__ __launch_bounds__(1024) void k_scan() {
    __shared__ int sh_warp[32];
    __shared__ int sh_carry;
    const int tid = threadIdx.x, lane = tid & 31, wid = tid >> 5;
    if (tid == 0) sh_carry = 0;
    __syncthreads();
    for (int base = 0; base < NN; base += 4096) {
        int idx = base + tid * 4;
        int4 c = make_int4(0, 0, 0, 0);
        if (idx < NN) c = *(const int4*)&g_cnt[idx];
        int t = c.x + c.y + c.z + c.w;
        int v = t;
#pragma unroll
        for (int o = 1; o < 32; o <<= 1) {
            int tt = __shfl_up_sync(0xffffffffu, v, o);
            if (lane >= o) v += tt;
        }
        if (lane == 31) sh_warp[wid] = v;
        __syncthreads();
        if (wid == 0) {
            int s = sh_warp[lane];
#pragma unroll
            for (int o = 1; o < 32; o <<= 1) {
                int tt = __shfl_up_sync(0xffffffffu, s, o);
                if (lane >= o) s += tt;
            }
            sh_warp[lane] = s;
        }
        __syncthreads();
        int warpoff = (wid > 0) ? sh_warp[wid - 1] : 0;
        int incl = v + warpoff;
        int excl = incl - t + sh_carry;
        if (idx < NN) {
            int4 off;
            off.x = excl;
            off.y = off.x + c.x;
            off.z = off.y + c.y;
            off.w = off.z + c.z;
            *(int4*)&g_off[idx] = off;
            float4 dv;
            dv.x = c.x ? rsqrtf((float)c.x) : 0.f;
            dv.y = c.y ? rsqrtf((float)c.y) : 0.f;
            dv.z = c.z ? rsqrtf((float)c.z) : 0.f;
            dv.w = c.w ? rsqrtf((float)c.w) : 0.f;
            *(float4*)&g_dinv[idx] = dv;
            *(int4*)&g_cnt[idx] = make_int4(0, 0, 0, 0);
        }
        __syncthreads();
        if (tid == 1023) sh_carry += incl;
        __syncthreads();
    }
    if (tid == 0) g_off[NN] = sh_carry;
}

__global__ void k_fill(const int* __restrict__ src, const int* __restrict__ dst, int E) {
    int e = blockIdx.x * blockDim.x + threadIdx.x;
    if (e < E) {
        int s = src[e], d = dst[e];
        int pos = g_off[d] + atomicAdd(&g_cnt[d], 1);
        g_csr_src[pos] = s;
        g_norm[pos] = g_dinv[s] * g_dinv[d];
    }
}

// ---------------- packing helpers ----------------
__device__ __forceinline__ uint32_t pkbf(float a, float b) {
    __nv_bfloat162 t;
    t.x = __float2bfloat16_rn(a);
    t.y = __float2bfloat16_rn(b);
    return *(uint32_t*)&t;
}

// ---------------- W split + interleave (permuted kpair slots) ----------------
__global__ void k_wconv(const float* __restrict__ W) {
    int i = blockIdx.x * blockDim.x + threadIdx.x;
    if (i >= HIDDEN * 256) return;
    int m = i >> 8;
    int pg = i & 255;
    int c = pg >> 5;
    int p = pg & 31;
    float w0 = W[m * IN_DIM + c * 64 + 2 * p];
    float w1 = W[m * IN_DIM + c * 64 + 2 * p + 1];
    float h0 = __bfloat162float(__float2bfloat16_rn(w0));
    float h1 = __bfloat162float(__float2bfloat16_rn(w1));
    uint2 v;
    v.x = pkbf(w0, w1);
    v.y = pkbf(w0 - h0, w1 - h1);
    g_wsplit[(size_t)c * CHUNK_U2 + m * APITCH + kperm(p)] = v;
}

// ---------------- GEMM1 via mma.sync bf16-split, cp.async W, occ-2, LDS.128 frags ----------------
#define GEMM1_DSMEM (2 * CHUNK_U2 * 8)

__device__ __forceinline__ void mma_bf16(float* c, uint32_t a0, uint32_t a1,
                                         uint32_t a2, uint32_t a3,
                                         uint32_t b0, uint32_t b1) {
    asm volatile(
        "mma.sync.aligned.m16n8k16.row.col.f32.bf16.bf16.f32 "
        "{%0,%1,%2,%3}, {%4,%5,%6,%7}, {%8,%9}, {%0,%1,%2,%3};"
        : "+f"(c[0]), "+f"(c[1]), "+f"(c[2]), "+f"(c[3])
        : "r"(a0), "r"(a1), "r"(a2), "r"(a3), "r"(b0), "r"(b1));
}

__global__ __launch_bounds__(256, 2) void k_gemm1_mma(const float* __restrict__ X,
                                                      const float* __restrict__ Bias,
                                                      const float* __restrict__ attL,
                                                      const float* __restrict__ attR,
                                                      float* __restrict__ al_out,
                                                      float* __restrict__ ar_out,
                                                      float* __restrict__ O,
                                                      uint32_t* __restrict__ O16,
                                                      int M) {
    extern __shared__ uint2 sm[];
    uint2* smA = sm;
    uint2* smW = sm + CHUNK_U2;
    __shared__ float sBias[128], sAtl[128], sAtr[128];

    const int tid = threadIdx.x;
    const int wt = tid >> 5;
    const int lane = tid & 31;
    const int r = lane >> 2;
    const int q = lane & 3;
    const int m0 = blockIdx.x * 128;

    uint32_t smW_u32;
    asm("{ .reg .u64 t; cvta.to.shared.u64 t, %1; cvt.u32.u64 %0, t; }"
        : "=r"(smW_u32) : "l"((void*)smW));

    if (tid < 128) {
        sBias[tid] = Bias[tid];
        sAtl[tid] = attL[tid];
        sAtr[tid] = attR[tid];
    }

    const int srow = tid >> 1;
    const int shalf = tid & 1;
    int gm = m0 + srow;
    if (gm >= M) gm = M - 1;
    const float* xrow = X + (size_t)gm * IN_DIM + shalf * 32;
    uint2* sa = smA + srow * APITCH + shalf * 16;   // local slots computed per write

    // uint4 views: 17 uint4 per row (APITCH=34 uint2)
    const uint4* smA4 = (const uint4*)smA;
    const uint4* smW4 = (const uint4*)smW;
    const int aIdx0 = (wt * 16 + r) * 17 + q;        // + k16*4, +8*17 for hi row
    const int wIdx0 = r * 17 + q;                    // + nt*8*17 + k16*4

    float acc[16][4];
#pragma unroll
    for (int i = 0; i < 16; i++)
#pragma unroll
        for (int j = 0; j < 4; j++) acc[i][j] = 0.f;

    {
        const uint2* gW = g_wsplit;
        for (int i = tid; i < 2176; i += 256)
            asm volatile("cp.async.cg.shared.global [%0], [%1], 16;"
                         :: "r"(smW_u32 + i * 16), "l"(gW + (size_t)i * 2));
        asm volatile("cp.async.commit_group;" ::: "memory");
    }

    for (int c = 0; c < IN_DIM / 64; c++) {
        const int kc = c * 64;
        // stage A: 32 floats -> 16 uint2 at permuted slots
#pragma unroll
        for (int g = 0; g < 8; g++) {
            float4 v = *(const float4*)(xrow + kc + g * 4);
            float h0 = __bfloat162float(__float2bfloat16_rn(v.x));
            float h1 = __bfloat162float(__float2bfloat16_rn(v.y));
            float h2 = __bfloat162float(__float2bfloat16_rn(v.z));
            float h3 = __bfloat162float(__float2bfloat16_rn(v.w));
            uint2 p0, p1;
            p0.x = pkbf(v.x, v.y);
            p0.y = pkbf(v.x - h0, v.y - h1);
            p1.x = pkbf(v.z, v.w);
            p1.y = pkbf(v.z - h2, v.w - h3);
            int j0 = g * 2;        // local kpair (0..15), global p = shalf*16 + j
            int j1 = g * 2 + 1;
            int s0 = (j0 & ~7) | (((j0 & 3) << 1) | ((j0 >> 2) & 1));
            int s1 = (j1 & ~7) | (((j1 & 3) << 1) | ((j1 >> 2) & 1));
            sa[s0] = p0;
            sa[s1] = p1;
        }
        asm volatile("cp.async.wait_group 0;" ::: "memory");
        __syncthreads();

#pragma unroll
        for (int k16 = 0; k16 < 4; k16++) {
            // A fragments: one LDS.128 per row-half
            uint4 aLo = smA4[aIdx0 + k16 * 4];             // row r:   (hi_q, lo_q, hi_q4, lo_q4)
            uint4 aHi = smA4[aIdx0 + 8 * 17 + k16 * 4];    // row r+8
            const uint32_t ah0 = aLo.x, ah1 = aHi.x, ah2 = aLo.z, ah3 = aHi.z;
            const uint32_t al0 = aLo.y, al1 = aHi.y, al2 = aLo.w, al3 = aHi.w;
            int wIdx = wIdx0 + k16 * 4;
#pragma unroll
            for (int nt = 0; nt < 16; nt++) {
                uint4 u = smW4[wIdx + nt * 136];           // (whq, wlq, whq4, wlq4)
                mma_bf16(acc[nt], ah0, ah1, ah2, ah3, u.x, u.z);  // ah*wh
                mma_bf16(acc[nt], ah0, ah1, ah2, ah3, u.y, u.w);  // ah*wl
                mma_bf16(acc[nt], al0, al1, al2, al3, u.x, u.z);  // al*wh
            }
        }
        __syncthreads();
        if (c + 1 < IN_DIM / 64) {
            const uint2* gW = g_wsplit + (size_t)(c + 1) * CHUNK_U2;
            for (int i = tid; i < 2176; i += 256)
                asm volatile("cp.async.cg.shared.global [%0], [%1], 16;"
                             :: "r"(smW_u32 + i * 16), "l"(gW + (size_t)i * 2));
            asm volatile("cp.async.commit_group;" ::: "memory");
        }
    }

    int mlo = m0 + wt * 16 + r;
    int mhi = mlo + 8;
    float slLo = 0.f, srLo = 0.f, slHi = 0.f, srHi = 0.f;
#pragma unroll
    for (int nt = 0; nt < 16; nt++) {
        int c0 = nt * 8 + q * 2;
        float b0 = sBias[c0], b1 = sBias[c0 + 1];
        float l0 = sAtl[c0], l1 = sAtl[c0 + 1];
        float t0 = sAtr[c0], t1 = sAtr[c0 + 1];
        float v0 = fmaxf(acc[nt][0] + b0, 0.f);
        float v1 = fmaxf(acc[nt][1] + b1, 0.f);
        float v2 = fmaxf(acc[nt][2] + b0, 0.f);
        float v3 = fmaxf(acc[nt][3] + b1, 0.f);
        slLo = fmaf(v0, l0, fmaf(v1, l1, slLo));
        srLo = fmaf(v0, t0, fmaf(v1, t1, srLo));
        slHi = fmaf(v2, l0, fmaf(v3, l1, slHi));
        srHi = fmaf(v2, t0, fmaf(v3, t1, srHi));
        if (mlo < M) {
            *(float2*)(O + (size_t)mlo * HIDDEN + c0) = make_float2(v0, v1);
            __half2 hp = __floats2half2_rn(v0, v1);
            O16[((size_t)mlo * HIDDEN + c0) >> 1] = *(uint32_t*)&hp;
        }
        if (mhi < M) {
            *(float2*)(O + (size_t)mhi * HIDDEN + c0) = make_float2(v2, v3);
            __half2 hp = __floats2half2_rn(v2, v3);
            O16[((size_t)mhi * HIDDEN + c0) >> 1] = *(uint32_t*)&hp;
        }
    }
#pragma unroll
    for (int o = 1; o <= 2; o <<= 1) {
        slLo += __shfl_xor_sync(0xffffffffu, slLo, o);
        srLo += __shfl_xor_sync(0xffffffffu, srLo, o);
        slHi += __shfl_xor_sync(0xffffffffu, slHi, o);
        srHi += __shfl_xor_sync(0xffffffffu, srHi, o);
    }
    if (q == 0) {
        if (mlo < M) { al_out[mlo] = slLo; ar_out[mlo] = srLo; }
        if (mhi < M) { al_out[mhi] = slHi; ar_out[mhi] = srHi; }
    }
}

// ---------------- aggregation: warp-per-node, fp16 rows, 2-way unrolled loads ----------------
__global__ __launch_bounds__(256) void k_gather(const uint2* __restrict__ h16,
                                                const float4* __restrict__ raw4,
                                                uint2* __restrict__ o16,
                                                float4* __restrict__ o4,
                                                const float* __restrict__ al_in,
                                                const float* __restrict__ ar_in,
                                                const float4* __restrict__ attl_next,
                                                const float4* __restrict__ attr_next,
                                                float* __restrict__ al_out,
                                                float* __restrict__ ar_out,
                                                int M) {
    int w = (blockIdx.x * blockDim.x + threadIdx.x) >> 5;
    int lane = threadIdx.x & 31;
    if (w >= M) return;
    int b = g_off[w];
    int e = g_off[w + 1];
    float ar_w = ar_in[w];
    float4 r = raw4[(size_t)w * 32 + lane];
    float4 acc;
    acc.x = EPS * r.x; acc.y = EPS * r.y; acc.z = EPS * r.z; acc.w = EPS * r.w;

    for (int j0 = b; j0 < e; j0 += 32) {
        int jj = j0 + lane;
        float cl = 0.f;
        int sl = 0;
        if (jj < e) {
            sl = __ldg(&g_csr_src[jj]);
            float nrm = __ldg(&g_norm[jj]);
            cl = tanhf(al_in[sl] + ar_w) * nrm;
        }
        int cnt = min(32, e - j0);
        int k = 0;
        for (; k + 2 <= cnt; k += 2) {
            float c0 = __shfl_sync(0xffffffffu, cl, k);
            float c1 = __shfl_sync(0xffffffffu, cl, k + 1);
            int s0 = __shfl_sync(0xffffffffu, sl, k);
            int s1 = __shfl_sync(0xffffffffu, sl, k + 1);
            uint2 hv0 = __ldg(&h16[(size_t)s0 * 32 + lane]);
            uint2 hv1 = __ldg(&h16[(size_t)s1 * 32 + lane]);
            float2 a0 = __half22float2(*(__half2*)&hv0.x);
            float2 a1 = __half22float2(*(__half2*)&hv0.y);
            float2 b0 = __half22float2(*(__half2*)&hv1.x);
            float2 b1 = __half22float2(*(__half2*)&hv1.y);
            acc.x = fmaf(c0, a0.x, acc.x);
            acc.y = fmaf(c0, a0.y, acc.y);
            acc.z = fmaf(c0, a1.x, acc.z);
            acc.w = fmaf(c0, a1.y, acc.w);
            acc.x = fmaf(c1, b0.x, acc.x);
            acc.y = fmaf(c1, b0.y, acc.y);
            acc.z = fmaf(c1, b1.x, acc.z);
            acc.w = fmaf(c1, b1.y, acc.w);
        }
        if (k < cnt) {
            float c = __shfl_sync(0xffffffffu, cl, k);
            int s = __shfl_sync(0xffffffffu, sl, k);
            uint2 hv = __ldg(&h16[(size_t)s * 32 + lane]);
            float2 f0 = __half22float2(*(__half2*)&hv.x);
            float2 f1 = __half22float2(*(__half2*)&hv.y);
            acc.x = fmaf(c, f0.x, acc.x);
            acc.y = fmaf(c, f0.y, acc.y);
            acc.z = fmaf(c, f1.x, acc.z);
            acc.w = fmaf(c, f1.y, acc.w);
        }
    }
    if (o16) {
        __half2 p0 = __floats2half2_rn(acc.x, acc.y);
        __half2 p1 = __floats2half2_rn(acc.z, acc.w);
        uint2 ov;
        ov.x = *(uint32_t*)&p0;
        ov.y = *(uint32_t*)&p1;
        o16[(size_t)w * 32 + lane] = ov;
    }
    if (o4) o4[(size_t)w * 32 + lane] = acc;

    if (attl_next) {
        float4 wl = attl_next[lane];
        float4 wr = attr_next[lane];
        float a = acc.x * wl.x + acc.y * wl.y + acc.z * wl.z + acc.w * wl.w;
        float bb = acc.x * wr.x + acc.y * wr.y + acc.z * wr.z + acc.w * wr.w;
#pragma unroll
        for (int o = 16; o > 0; o >>= 1) {
            a += __shfl_xor_sync(0xffffffffu, a, o);
            bb += __shfl_xor_sync(0xffffffffu, bb, o);
        }
        if (lane == 0) { al_out[w] = a; ar_out[w] = bb; }
    }
}

// ---------------- GEMM2 + fused log_softmax ----------------
__global__ __launch_bounds__(256) void k_gemm2(const float* __restrict__ H,
                                               const float* __restrict__ W,
                                               const float* __restrict__ B,
                                               float* __restrict__ Emb,
                                               float* __restrict__ Ls, int M) {
    __shared__ float As[16][64];
    __shared__ float Bs[16][64];
    const int tid = threadIdx.x;
    const int m0 = blockIdx.x * 64;
    const int lr = tid >> 2;
    const int lk = (tid & 3) * 4;
    const int tm = (tid >> 4) * 4;
    const int tn = (tid & 15) * 4;

    int gm = m0 + lr;
    if (gm >= M) gm = M - 1;
    const float* hp = H + (size_t)gm * HIDDEN + lk;
    const float* wp = W + (size_t)lr * HIDDEN + lk;

    float acc[4][4];
#pragma unroll
    for (int i = 0; i < 4; i++)
#pragma unroll
        for (int j = 0; j < 4; j++) acc[i][j] = 0.f;

    for (int k0 = 0; k0 < HIDDEN; k0 += 16) {
        float4 xa = *(const float4*)(hp + k0);
        float4 wa = *(const float4*)(wp + k0);
        As[lk + 0][lr] = xa.x; As[lk + 1][lr] = xa.y;
        As[lk + 2][lr] = xa.z; As[lk + 3][lr] = xa.w;
        Bs[lk + 0][lr] = wa.x; Bs[lk + 1][lr] = wa.y;
        Bs[lk + 2][lr] = wa.z; Bs[lk + 3][lr] = wa.w;
        __syncthreads();
#pragma unroll
        for (int kk = 0; kk < 16; kk++) {
            float4 a4 = *(const float4*)&As[kk][tm];
            float4 b4 = *(const float4*)&Bs[kk][tn];
            float a[4] = {a4.x, a4.y, a4.z, a4.w};
            float b[4] = {b4.x, b4.y, b4.z, b4.w};
#pragma unroll
            for (int i = 0; i < 4; i++)
#pragma unroll
                for (int j = 0; j < 4; j++) acc[i][j] = fmaf(a[i], b[j], acc[i][j]);
        }
        __syncthreads();
    }

    float bias[4];
#pragma unroll
    for (int j = 0; j < 4; j++) bias[j] = B[tn + j];

#pragma unroll
    for (int i = 0; i < 4; i++) {
        int m = m0 + tm + i;
        float v[4];
#pragma unroll
        for (int j = 0; j < 4; j++) v[j] = acc[i][j] + bias[j];
        float mx = fmaxf(fmaxf(v[0], v[1]), fmaxf(v[2], v[3]));
#pragma unroll
        for (int o = 8; o > 0; o >>= 1) mx = fmaxf(mx, __shfl_xor_sync(0xffffffffu, mx, o));
        float s = expf(v[0] - mx) + expf(v[1] - mx) + expf(v[2] - mx) + expf(v[3] - mx);
#pragma unroll
        for (int o = 8; o > 0; o >>= 1) s += __shfl_xor_sync(0xffffffffu, s, o);
        float lse = mx + logf(s);
        if (m < M) {
            *(float4*)(Emb + (size_t)m * OUT_DIM + tn) = make_float4(v[0], v[1], v[2], v[3]);
            *(float4*)(Ls + (size_t)m * OUT_DIM + tn) =
                make_float4(v[0] - lse, v[1] - lse, v[2] - lse, v[3] - lse);
        }
    }
}

// ---------------- launch ----------------
extern "C" void kernel_launch(void* const* d_in, const int* in_sizes, int n_in,
                              void* d_out, int out_size) {
    const float* x    = (const float*)d_in[0];
    const int*   ei   = (const int*)  d_in[1];
    const float* t1w  = (const float*)d_in[2];
    const float* t1b  = (const float*)d_in[3];
    const float* t2w  = (const float*)d_in[4];
    const float* t2b  = (const float*)d_in[5];
    const float* attl = (const float*)d_in[6];
    const float* attr = (const float*)d_in[7];

    const int M = in_sizes[0] / IN_DIM;   // 50000
    const int E = in_sizes[1] / 2;        // 600000
    const int* src = ei;
    const int* dst = ei + E;

    float *raw, *hF, *alA, *arA, *alB, *arB;
    uint2 *h16R, *h16A, *h16B;
    int* cntp;
    cudaGetSymbolAddress((void**)&raw, g_raw);
    cudaGetSymbolAddress((void**)&hF, g_hF);
    cudaGetSymbolAddress((void**)&h16R, g_h16R);
    cudaGetSymbolAddress((void**)&h16A, g_h16A);
    cudaGetSymbolAddress((void**)&h16B, g_h16B);
    cudaGetSymbolAddress((void**)&alA, g_alA);
    cudaGetSymbolAddress((void**)&arA, g_arA);
    cudaGetSymbolAddress((void**)&alB, g_alB);
    cudaGetSymbolAddress((void**)&arB, g_arB);
    cudaGetSymbolAddress((void**)&cntp, g_cnt);

    float* out_ls  = (float*)d_out;
    float* out_emb = out_ls + (size_t)M * OUT_DIM;

    cudaFuncSetAttribute(k_gemm1_mma, cudaFuncAttributeMaxDynamicSharedMemorySize,
                         GEMM1_DSMEM);

    static cudaStream_t s2 = nullptr;
    static cudaEvent_t evFork = nullptr, evJoin = nullptr;
    if (!s2) {
        cudaStreamCreateWithFlags(&s2, cudaStreamNonBlocking);
        cudaEventCreateWithFlags(&evFork, cudaEventDisableTiming);
        cudaEventCreateWithFlags(&evJoin, cudaEventDisableTiming);
    }

    // k_gemm1_mma stays the 4th kernel launch (ncu capture target).
    k_wconv<<<(HIDDEN * 256 + 255) / 256, 256>>>(t1w);          // (1) main

    cudaEventRecord(evFork, 0);
    cudaStreamWaitEvent(s2, evFork, 0);
    cudaMemsetAsync(cntp, 0, NN * sizeof(int), s2);
    k_count<<<(E + 255) / 256, 256, 0, s2>>>(dst, E);           // (2) s2
    k_scan<<<1, 1024, 0, s2>>>();                               // (3) s2

    k_gemm1_mma<<<(M + 127) / 128, 256, GEMM1_DSMEM>>>(x, t1b, attl, attr, alA, arA,
                                                       raw, (uint32_t*)h16R, M);  // (4) main

    k_fill<<<(E + 255) / 256, 256, 0, s2>>>(src, dst, E);       // (5) s2
    cudaEventRecord(evJoin, s2);
    cudaStreamWaitEvent(0, evJoin, 0);

    // layer 0: read h16R -> write h16A (fp16 only)
    k_gather<<<((size_t)M * 32 + 255) / 256, 256>>>(h16R, (const float4*)raw,
                                                    h16A, nullptr,
                                                    alA, arA,
                                                    (const float4*)(attl + HIDDEN),
                                                    (const float4*)(attr + HIDDEN),
                                                    alB, arB, M);
    // layer 1: read h16A -> write h16B (fp16 only)
    k_gather<<<((size_t)M * 32 + 255) / 256, 256>>>(h16A, (const float4*)raw,
                                                    h16B, nullptr,
                                                    alB, arB,
                                                    (const float4*)(attl + 2 * HIDDEN),
                                                    (const float4*)(attr + 2 * HIDDEN),
                                                    alA, arA, M);
    // layer 2: read h16B -> write fp32 hF (for GEMM2)
    k_gather<<<((size_t)M * 32 + 255) / 256, 256>>>(h16B, (const float4*)raw,
                                                    nullptr, (float4*)hF,
                                                    alA, arA,
                                                    nullptr, nullptr,
                                                    nullptr, nullptr, M);

    k_gemm2<<<(M + 63) / 64, 256>>>(hF, t2w, t2b, out_emb, out_ls, M);
}